// round 4
// baseline (speedup 1.0000x reference)
#include <cuda_runtime.h>
#include <cuda_bf16.h>
#include <cstdint>

#define BATCH 4
#define SEQ   2048
#define DIM   1024

typedef __nv_bfloat16 bf16;

// ---------------- scratch (device globals; allocation-free) ----------------
__device__ __align__(128) bf16  g_xh[(long)BATCH*SEQ*DIM];
__device__ __align__(128) bf16  g_xl[(long)BATCH*SEQ*DIM];
__device__ __align__(128) bf16  g_wh[3][(long)DIM*DIM];
__device__ __align__(128) bf16  g_wl[3][(long)DIM*DIM];
__device__ __align__(128) bf16  g_qh[(long)BATCH*SEQ*DIM];
__device__ __align__(128) bf16  g_ql[(long)BATCH*SEQ*DIM];
__device__ __align__(128) bf16  g_kh[(long)BATCH*SEQ*DIM];
__device__ __align__(128) bf16  g_kl[(long)BATCH*SEQ*DIM];
__device__ __align__(128) bf16  g_vth[(long)BATCH*SEQ*DIM];   // V^T: [b][e][s]
__device__ __align__(128) bf16  g_vtl[(long)BATCH*SEQ*DIM];
__device__ __align__(128) float g_sc [(long)BATCH*SEQ*SEQ];
__device__ __align__(128) bf16  g_ph [(long)BATCH*SEQ*SEQ];
__device__ __align__(128) bf16  g_pl [(long)BATCH*SEQ*SEQ];

// ---------------- PTX helpers (arch-generic; NO tcgen05) ----------------
__device__ __forceinline__ uint32_t smem_u32(const void* p) {
    uint32_t a;
    asm("{ .reg .u64 t; cvta.to.shared.u64 t, %1; cvt.u32.u64 %0, t; }" : "=r"(a) : "l"(p));
    return a;
}
__device__ __forceinline__ void cp16(uint32_t saddr, const void* g) {
    asm volatile("cp.async.cg.shared.global [%0], [%1], 16;" :: "r"(saddr), "l"(g) : "memory");
}
#define CP_COMMIT() asm volatile("cp.async.commit_group;" ::: "memory")

__device__ __forceinline__ void ldsm_x4(uint32_t* r, uint32_t addr) {
    asm volatile("ldmatrix.sync.aligned.m8n8.x4.shared.b16 {%0,%1,%2,%3}, [%4];"
        : "=r"(r[0]), "=r"(r[1]), "=r"(r[2]), "=r"(r[3]) : "r"(addr));
}
__device__ __forceinline__ void mma16816(float* c, const uint32_t* a, const uint32_t* b) {
    asm volatile("mma.sync.aligned.m16n8k16.row.col.f32.bf16.bf16.f32 "
        "{%0,%1,%2,%3}, {%4,%5,%6,%7}, {%8,%9}, {%0,%1,%2,%3};"
        : "+f"(c[0]), "+f"(c[1]), "+f"(c[2]), "+f"(c[3])
        : "r"(a[0]), "r"(a[1]), "r"(a[2]), "r"(a[3]), "r"(b[0]), "r"(b[1]));
}

// byte offset inside an 8KB tile of [128 rows][32 bf16], 64B rows,
// 16B chunks XOR-swizzled for conflict-free ldmatrix + stores
__device__ __forceinline__ uint32_t swz(int row, int kc) {
    return (uint32_t)(row * 64 + ((kc ^ ((row >> 1) & 3)) << 4));
}

// ---------------- SMEM layout ----------------
// mainloop: 4 stages x 32KB: [Ahi 8K | Alo 8K | Bhi 8K | Blo 8K]
// epilogue: float buf[128][EPI_LD] overlaps stage memory
#define STAGES 4
#define STAGE_BYTES 32768
#define EPI_LD 132
#define SMEM_TOTAL (STAGES * STAGE_BYTES)   // 131072 >= 128*132*4 = 67584

// =====================================================================
// bf16x3 NT GEMM via mma.sync:  C_tile[128,128] = A[128,K] @ B[128,K]^T
// mode 0: fp32 C;  mode 1: bf16 hi/lo C;  mode 2: bf16 hi/lo C transposed
// =====================================================================
__global__ void __launch_bounds__(256) gemm_bf16x3(
    const bf16* __restrict__ Ahi, const bf16* __restrict__ Alo,
    const bf16* __restrict__ Bhi, const bf16* __restrict__ Blo,
    float* __restrict__ Cf, bf16* __restrict__ Chi, bf16* __restrict__ Clo,
    int K, int ldA, int ldB, int ldC,
    long strideA, long strideB, long strideC,
    int causal, int kclamp, int mode)
{
    const int bx = blockIdx.x, by = blockIdx.y, bz = blockIdx.z;
    if (causal && bx > by) return;

    extern __shared__ char smem[];
    const uint32_t sbase = smem_u32(smem);
    const int tid  = threadIdx.x;
    const int lane = tid & 31;
    const int wid  = tid >> 5;
    const int wm   = wid >> 2;   // 0..1 : 64 rows
    const int wn   = wid & 3;    // 0..3 : 32 cols

    const int kmax    = kclamp ? min(K, (by + 1) * 128) : K;
    const int nchunks = kmax >> 5;                // BK = 32

    const bf16* pAh = Ahi + bz * strideA + (long)by * 128 * ldA;
    const bf16* pAl = Alo + bz * strideA + (long)by * 128 * ldA;
    const bf16* pBh = Bhi + bz * strideB + (long)bx * 128 * ldB;
    const bf16* pBl = Blo + bz * strideB + (long)bx * 128 * ldB;

    // per-thread load coords: 512 16B-chunks per 8KB tile, 2 per thread
    const int l_row0 = tid >> 2,         l_kc0 = tid & 3;
    const int l_row1 = (tid + 256) >> 2, l_kc1 = (tid + 256) & 3;

    auto load_chunk = [&](int c) {
        const uint32_t st = sbase + (uint32_t)(c & (STAGES - 1)) * STAGE_BYTES;
        const int k0 = c << 5;
        {
            long gA = (long)l_row0 * ldA + k0 + l_kc0 * 8;
            long gB = (long)l_row0 * ldB + k0 + l_kc0 * 8;
            uint32_t so = swz(l_row0, l_kc0);
            cp16(st +         so, pAh + gA);
            cp16(st +  8192 + so, pAl + gA);
            cp16(st + 16384 + so, pBh + gB);
            cp16(st + 24576 + so, pBl + gB);
        }
        {
            long gA = (long)l_row1 * ldA + k0 + l_kc1 * 8;
            long gB = (long)l_row1 * ldB + k0 + l_kc1 * 8;
            uint32_t so = swz(l_row1, l_kc1);
            cp16(st +         so, pAh + gA);
            cp16(st +  8192 + so, pAl + gA);
            cp16(st + 16384 + so, pBh + gB);
            cp16(st + 24576 + so, pBl + gB);
        }
        CP_COMMIT();
    };

    float acc[4][4][4];
    #pragma unroll
    for (int i = 0; i < 4; i++)
        #pragma unroll
        for (int j = 0; j < 4; j++)
            #pragma unroll
            for (int p = 0; p < 4; p++) acc[i][j][p] = 0.f;

    // prologue: fill 3 stages
    load_chunk(0);
    if (nchunks > 1) load_chunk(1);
    if (nchunks > 2) load_chunk(2);

    const int lrow = lane & 15;
    const int lsel = lane >> 4;

    for (int c = 0; c < nchunks; c++) {
        // pending groups allowed = min(2, nchunks-1-c); wait for chunk c.
        const int rem = nchunks - 1 - c;
        if (rem >= 2)      asm volatile("cp.async.wait_group 2;" ::: "memory");
        else if (rem == 1) asm volatile("cp.async.wait_group 1;" ::: "memory");
        else               asm volatile("cp.async.wait_group 0;" ::: "memory");
        __syncthreads();   // single barrier per chunk: also retires all reads
                           // of stage (c-1), which load_chunk(c+3) overwrites.

        const uint32_t st  = sbase + (uint32_t)(c & (STAGES - 1)) * STAGE_BYTES;
        const uint32_t sAh = st, sAl = st + 8192, sBh = st + 16384, sBl = st + 24576;

        #pragma unroll
        for (int ks = 0; ks < 2; ks++) {
            const int kc = ks * 2 + lsel;
            uint32_t a_hi[4][4], a_lo[4][4], bh[4][2], bl[4][2];
            #pragma unroll
            for (int mt = 0; mt < 4; mt++) {
                int r = wm * 64 + mt * 16 + lrow;
                ldsm_x4(a_hi[mt], sAh + swz(r, kc));
                ldsm_x4(a_lo[mt], sAl + swz(r, kc));
            }
            #pragma unroll
            for (int np = 0; np < 2; np++) {
                int r = wn * 32 + np * 16 + lrow;
                uint32_t t4[4];
                ldsm_x4(t4, sBh + swz(r, kc));
                bh[np*2][0] = t4[0]; bh[np*2][1] = t4[2];
                bh[np*2+1][0] = t4[1]; bh[np*2+1][1] = t4[3];
                ldsm_x4(t4, sBl + swz(r, kc));
                bl[np*2][0] = t4[0]; bl[np*2][1] = t4[2];
                bl[np*2+1][0] = t4[1]; bl[np*2+1][1] = t4[3];
            }
            #pragma unroll
            for (int mt = 0; mt < 4; mt++)
                #pragma unroll
                for (int nt = 0; nt < 4; nt++)
                    mma16816(acc[mt][nt], a_hi[mt], bh[nt]);
            #pragma unroll
            for (int mt = 0; mt < 4; mt++)
                #pragma unroll
                for (int nt = 0; nt < 4; nt++)
                    mma16816(acc[mt][nt], a_hi[mt], bl[nt]);
            #pragma unroll
            for (int mt = 0; mt < 4; mt++)
                #pragma unroll
                for (int nt = 0; nt < 4; nt++)
                    mma16816(acc[mt][nt], a_lo[mt], bh[nt]);
        }
        if (c + 3 < nchunks) load_chunk(c + 3);
    }

    // ---- epilogue: stage fp32 tile in smem, then coalesced global writes ----
    __syncthreads();   // protect stage memory before reuse as epilogue buffer
    float* buf = (float*)smem;
    {
        const int rq = lane >> 2;          // 0..7
        const int cq = (lane & 3) * 2;     // 0,2,4,6
        #pragma unroll
        for (int mt = 0; mt < 4; mt++)
            #pragma unroll
            for (int nt = 0; nt < 4; nt++) {
                int r0 = wm * 64 + mt * 16 + rq;
                int c0 = wn * 32 + nt * 8 + cq;
                *(float2*)&buf[r0 * EPI_LD + c0]       = make_float2(acc[mt][nt][0], acc[mt][nt][1]);
                *(float2*)&buf[(r0 + 8) * EPI_LD + c0] = make_float2(acc[mt][nt][2], acc[mt][nt][3]);
            }
    }
    __syncthreads();

    if (mode == 0) {
        int r = tid >> 1, c0 = (tid & 1) * 64;
        long row = (long)by * 128 + r;
        float4* dst = (float4*)(Cf + bz * strideC + row * ldC + (long)bx * 128 + c0);
        #pragma unroll
        for (int i = 0; i < 16; i++)
            dst[i] = *(float4*)&buf[r * EPI_LD + c0 + i * 4];
    } else if (mode == 1) {
        int r = tid >> 1, c0 = (tid & 1) * 64;
        long row = (long)by * 128 + r;
        bf16* dh = Chi + bz * strideC + row * ldC + (long)bx * 128 + c0;
        bf16* dl = Clo + bz * strideC + row * ldC + (long)bx * 128 + c0;
        #pragma unroll
        for (int v = 0; v < 8; v++) {
            uint4 uh, ul;
            uint32_t* ph = (uint32_t*)&uh; uint32_t* pl = (uint32_t*)&ul;
            #pragma unroll
            for (int p = 0; p < 4; p++) {
                float f0 = buf[r * EPI_LD + c0 + v * 8 + p * 2];
                float f1 = buf[r * EPI_LD + c0 + v * 8 + p * 2 + 1];
                bf16 h0 = __float2bfloat16(f0), h1 = __float2bfloat16(f1);
                bf16 l0 = __float2bfloat16(f0 - __bfloat162float(h0));
                bf16 l1 = __float2bfloat16(f1 - __bfloat162float(h1));
                ph[p] = (uint32_t)*(uint16_t*)&h0 | ((uint32_t)*(uint16_t*)&h1 << 16);
                pl[p] = (uint32_t)*(uint16_t*)&l0 | ((uint32_t)*(uint16_t*)&l1 << 16);
            }
            *(uint4*)(dh + v * 8) = uh;
            *(uint4*)(dl + v * 8) = ul;
        }
    } else {
        // transposed hi/lo out: Ct[e][s_local], batch derived from global row
        int cc = tid >> 1, s0 = (tid & 1) * 64;
        int rowbase = by * 128;
        int b = rowbase / SEQ;
        int sloc = (rowbase % SEQ) + s0;
        long e = (long)bx * 128 + cc;
        bf16* dh = Chi + b * strideC + e * ldC + sloc;
        bf16* dl = Clo + b * strideC + e * ldC + sloc;
        #pragma unroll
        for (int v = 0; v < 8; v++) {
            uint4 uh, ul;
            uint32_t* ph = (uint32_t*)&uh; uint32_t* pl = (uint32_t*)&ul;
            #pragma unroll
            for (int p = 0; p < 4; p++) {
                float f0 = buf[(s0 + v * 8 + p * 2)     * EPI_LD + cc];
                float f1 = buf[(s0 + v * 8 + p * 2 + 1) * EPI_LD + cc];
                bf16 h0 = __float2bfloat16(f0), h1 = __float2bfloat16(f1);
                bf16 l0 = __float2bfloat16(f0 - __bfloat162float(h0));
                bf16 l1 = __float2bfloat16(f1 - __bfloat162float(h1));
                ph[p] = (uint32_t)*(uint16_t*)&h0 | ((uint32_t)*(uint16_t*)&h1 << 16);
                pl[p] = (uint32_t)*(uint16_t*)&l0 | ((uint32_t)*(uint16_t*)&l1 << 16);
            }
            *(uint4*)(dh + v * 8) = uh;
            *(uint4*)(dl + v * 8) = ul;
        }
    }
}

// ---------------- fp32 -> bf16 hi/lo split ----------------
__global__ void __launch_bounds__(256) split_f32(
    const float* __restrict__ src, bf16* __restrict__ hi, bf16* __restrict__ lo, long n)
{
    long i = ((long)blockIdx.x * 256 + threadIdx.x) * 4;
    if (i >= n) return;
    float4 v = *(const float4*)(src + i);
    float f[4] = {v.x, v.y, v.z, v.w};
    uint32_t h2[2], l2[2];
    #pragma unroll
    for (int p = 0; p < 2; p++) {
        bf16 h0 = __float2bfloat16(f[p*2]),   h1 = __float2bfloat16(f[p*2+1]);
        bf16 l0 = __float2bfloat16(f[p*2]   - __bfloat162float(h0));
        bf16 l1 = __float2bfloat16(f[p*2+1] - __bfloat162float(h1));
        h2[p] = (uint32_t)*(uint16_t*)&h0 | ((uint32_t)*(uint16_t*)&h1 << 16);
        l2[p] = (uint32_t)*(uint16_t*)&l0 | ((uint32_t)*(uint16_t*)&l1 << 16);
    }
    *(uint2*)(hi + i) = make_uint2(h2[0], h2[1]);
    *(uint2*)(lo + i) = make_uint2(l2[0], l2[1]);
}

// ---------------- causal softmax: fp32 scores -> bf16 hi/lo probs ----------------
__global__ void __launch_bounds__(256) softmax_causal(
    const float* __restrict__ Sc, bf16* __restrict__ Ph, bf16* __restrict__ Pl)
{
    const long r = blockIdx.x;
    const int  q = (int)(r & (SEQ - 1));
    const float* row = Sc + r * SEQ;
    bf16* ph = Ph + r * SEQ;
    bf16* pl = Pl + r * SEQ;

    __shared__ float bufr[SEQ];
    __shared__ float red[256];

    const int tid = threadIdx.x;
    const int len = q + 1;
    const float scale = 0.03125f;  // 1/sqrt(1024)

    float m = -1e30f;
    for (int k = tid; k < len; k += 256) {
        float v = row[k] * scale;
        bufr[k] = v;
        m = fmaxf(m, v);
    }
    red[tid] = m;
    __syncthreads();
    #pragma unroll
    for (int s = 128; s > 0; s >>= 1) {
        if (tid < s) red[tid] = fmaxf(red[tid], red[tid + s]);
        __syncthreads();
    }
    m = red[0];
    __syncthreads();

    float sum = 0.f;
    for (int k = tid; k < len; k += 256) {
        float e = __expf(bufr[k] - m);
        bufr[k] = e;
        sum += e;
    }
    red[tid] = sum;
    __syncthreads();
    #pragma unroll
    for (int s = 128; s > 0; s >>= 1) {
        if (tid < s) red[tid] += red[tid + s];
        __syncthreads();
    }
    const float inv = 1.0f / red[0];
    __syncthreads();

    for (int k = tid; k < len; k += 256) {
        float p = bufr[k] * inv;
        bf16 h = __float2bfloat16(p);
        bf16 l = __float2bfloat16(p - __bfloat162float(h));
        ph[k] = h; pl[k] = l;
    }
    const bf16 z = __float2bfloat16(0.f);
    for (int k = len + tid; k < SEQ; k += 256) { ph[k] = z; pl[k] = z; }
}

// ---------------------------------------------------------------------------
extern "C" void kernel_launch(void* const* d_in, const int* in_sizes, int n_in,
                              void* d_out, int out_size)
{
    const float* X  = (const float*)d_in[0];
    const float* Wq = (const float*)d_in[1];
    const float* Wk = (const float*)d_in[2];
    const float* Wv = (const float*)d_in[3];
    float* out = (float*)d_out;

    bf16 *xh, *xl, *wh, *wl, *qh, *ql, *kh, *kl, *vth, *vtl, *ph, *pl;
    float *sc;
    cudaGetSymbolAddress((void**)&xh,  g_xh);  cudaGetSymbolAddress((void**)&xl,  g_xl);
    cudaGetSymbolAddress((void**)&wh,  g_wh);  cudaGetSymbolAddress((void**)&wl,  g_wl);
    cudaGetSymbolAddress((void**)&qh,  g_qh);  cudaGetSymbolAddress((void**)&ql,  g_ql);
    cudaGetSymbolAddress((void**)&kh,  g_kh);  cudaGetSymbolAddress((void**)&kl,  g_kl);
    cudaGetSymbolAddress((void**)&vth, g_vth); cudaGetSymbolAddress((void**)&vtl, g_vtl);
    cudaGetSymbolAddress((void**)&sc,  g_sc);
    cudaGetSymbolAddress((void**)&ph,  g_ph);  cudaGetSymbolAddress((void**)&pl,  g_pl);

    cudaFuncSetAttribute(gemm_bf16x3, cudaFuncAttributeMaxDynamicSharedMemorySize, SMEM_TOTAL);

    const long nX = (long)BATCH * SEQ * DIM;
    const long nW = (long)DIM * DIM;
    const long WW = nW;

    dim3 thr(256);
    split_f32<<<(unsigned)(nX / 1024), thr>>>(X,  xh,          xl,          nX);
    split_f32<<<(unsigned)(nW / 1024), thr>>>(Wq, wh + 0 * WW, wl + 0 * WW, nW);
    split_f32<<<(unsigned)(nW / 1024), thr>>>(Wk, wh + 1 * WW, wl + 1 * WW, nW);
    split_f32<<<(unsigned)(nW / 1024), thr>>>(Wv, wh + 2 * WW, wl + 2 * WW, nW);

    const int M = BATCH * SEQ;  // 8192

    // 1) projections  [8192,1024] = X @ W^T   (Q,K: mode 1; V: mode 2 transposed)
    dim3 gProj(DIM / 128, M / 128, 1);
    gemm_bf16x3<<<gProj, thr, SMEM_TOTAL>>>(xh, xl, wh + 0*WW, wl + 0*WW,
        nullptr, qh, ql, DIM, DIM, DIM, DIM, 0, 0, 0, 0, 0, 1);
    gemm_bf16x3<<<gProj, thr, SMEM_TOTAL>>>(xh, xl, wh + 1*WW, wl + 1*WW,
        nullptr, kh, kl, DIM, DIM, DIM, DIM, 0, 0, 0, 0, 0, 1);
    gemm_bf16x3<<<gProj, thr, SMEM_TOTAL>>>(xh, xl, wh + 2*WW, wl + 2*WW,
        nullptr, vth, vtl, DIM, DIM, DIM, SEQ, 0, 0, (long)DIM * SEQ, 0, 0, 2);

    // 2) scores = Q @ K^T per batch (causal tile skip), fp32 out
    dim3 gScore(SEQ / 128, SEQ / 128, BATCH);
    gemm_bf16x3<<<gScore, thr, SMEM_TOTAL>>>(qh, ql, kh, kl,
        sc, nullptr, nullptr, DIM, DIM, DIM, SEQ,
        (long)SEQ * DIM, (long)SEQ * DIM, (long)SEQ * SEQ, 1, 0, 0);

    // 3) softmax -> bf16 hi/lo probs
    softmax_causal<<<BATCH * SEQ, thr>>>(sc, ph, pl);

    // 4) out = P @ V^T per batch (causal k clamp), fp32 out
    dim3 gAV(DIM / 128, SEQ / 128, BATCH);
    gemm_bf16x3<<<gAV, thr, SMEM_TOTAL>>>(ph, pl, vth, vtl,
        out, nullptr, nullptr, SEQ, SEQ, SEQ, DIM,
        (long)SEQ * SEQ, (long)DIM * SEQ, (long)SEQ * DIM, 0, 1, 0);
}

// round 5
// speedup vs baseline: 1.0671x; 1.0671x over previous
#include <cuda_runtime.h>
#include <cuda_bf16.h>
#include <cstdint>

#define BATCH 4
#define SEQ   2048
#define DIM   1024

typedef __nv_bfloat16 bf16;

// ---------------- scratch (device globals; allocation-free) ----------------
__device__ __align__(128) bf16  g_xh[(long)BATCH*SEQ*DIM];
__device__ __align__(128) bf16  g_xl[(long)BATCH*SEQ*DIM];
__device__ __align__(128) bf16  g_wh[3][(long)DIM*DIM];
__device__ __align__(128) bf16  g_wl[3][(long)DIM*DIM];
__device__ __align__(128) bf16  g_qh[(long)BATCH*SEQ*DIM];
__device__ __align__(128) bf16  g_ql[(long)BATCH*SEQ*DIM];
__device__ __align__(128) bf16  g_kh[(long)BATCH*SEQ*DIM];
__device__ __align__(128) bf16  g_kl[(long)BATCH*SEQ*DIM];
__device__ __align__(128) bf16  g_vth[(long)BATCH*SEQ*DIM];   // V^T: [b][e][s]
__device__ __align__(128) bf16  g_vtl[(long)BATCH*SEQ*DIM];
__device__ __align__(128) float g_sc [(long)BATCH*SEQ*SEQ];
__device__ __align__(128) bf16  g_ph [(long)BATCH*SEQ*SEQ];
__device__ __align__(128) bf16  g_pl [(long)BATCH*SEQ*SEQ];

// ---------------- PTX helpers (arch-generic; NO tcgen05) ----------------
__device__ __forceinline__ uint32_t smem_u32(const void* p) {
    uint32_t a;
    asm("{ .reg .u64 t; cvta.to.shared.u64 t, %1; cvt.u32.u64 %0, t; }" : "=r"(a) : "l"(p));
    return a;
}
__device__ __forceinline__ void cp16(uint32_t saddr, const void* g) {
    asm volatile("cp.async.cg.shared.global [%0], [%1], 16;" :: "r"(saddr), "l"(g) : "memory");
}
#define CP_COMMIT() asm volatile("cp.async.commit_group;" ::: "memory")

__device__ __forceinline__ void ldsm_x4(uint32_t* r, uint32_t addr) {
    asm volatile("ldmatrix.sync.aligned.m8n8.x4.shared.b16 {%0,%1,%2,%3}, [%4];"
        : "=r"(r[0]), "=r"(r[1]), "=r"(r[2]), "=r"(r[3]) : "r"(addr));
}
__device__ __forceinline__ void mma16816(float* c, const uint32_t* a, const uint32_t* b) {
    asm volatile("mma.sync.aligned.m16n8k16.row.col.f32.bf16.bf16.f32 "
        "{%0,%1,%2,%3}, {%4,%5,%6,%7}, {%8,%9}, {%0,%1,%2,%3};"
        : "+f"(c[0]), "+f"(c[1]), "+f"(c[2]), "+f"(c[3])
        : "r"(a[0]), "r"(a[1]), "r"(a[2]), "r"(a[3]), "r"(b[0]), "r"(b[1]));
}

// byte offset inside an 8KB tile of [128 rows][32 bf16], 64B rows,
// 16B chunks XOR-swizzled for conflict-free ldmatrix + stores
__device__ __forceinline__ uint32_t swz(int row, int kc) {
    return (uint32_t)(row * 64 + ((kc ^ ((row >> 1) & 3)) << 4));
}

// ---------------- SMEM layout ----------------
// mainloop: 3 stages x 32KB: [Ahi 8K | Alo 8K | Bhi 8K | Blo 8K]
// epilogue: float buf[128][EPI_LD] overlaps stage memory
#define STAGES 3
#define STAGE_BYTES 32768
#define EPI_LD 132
#define SMEM_TOTAL (STAGES * STAGE_BYTES)   // 98304 >= 128*132*4 = 67584

// =====================================================================
// bf16x3 NT GEMM via mma.sync:  C_tile[128,128] = A[128,K] @ B[128,K]^T
// mode 0: fp32 C;  mode 1: bf16 hi/lo C;  mode 2: bf16 hi/lo C transposed
// =====================================================================
__global__ void __launch_bounds__(256, 2) gemm_bf16x3(
    const bf16* __restrict__ Ahi, const bf16* __restrict__ Alo,
    const bf16* __restrict__ Bhi, const bf16* __restrict__ Blo,
    float* __restrict__ Cf, bf16* __restrict__ Chi, bf16* __restrict__ Clo,
    int K, int ldA, int ldB, int ldC,
    long strideA, long strideB, long strideC,
    int causal, int kclamp, int mode)
{
    const int bx = blockIdx.x, by = blockIdx.y, bz = blockIdx.z;
    if (causal && bx > by) return;

    extern __shared__ char smem[];
    const uint32_t sbase = smem_u32(smem);
    const int tid  = threadIdx.x;
    const int lane = tid & 31;
    const int wid  = tid >> 5;
    const int wm   = wid >> 2;   // 0..1 : 64 rows
    const int wn   = wid & 3;    // 0..3 : 32 cols

    const int kmax    = kclamp ? min(K, (by + 1) * 128) : K;
    const int nchunks = kmax >> 5;                // BK = 32

    const bf16* pAh = Ahi + bz * strideA + (long)by * 128 * ldA;
    const bf16* pAl = Alo + bz * strideA + (long)by * 128 * ldA;
    const bf16* pBh = Bhi + bz * strideB + (long)bx * 128 * ldB;
    const bf16* pBl = Blo + bz * strideB + (long)bx * 128 * ldB;

    // per-thread load coords: 512 16B-chunks per 8KB tile, 2 per thread
    const int l_row0 = tid >> 2,         l_kc0 = tid & 3;
    const int l_row1 = (tid + 256) >> 2, l_kc1 = (tid + 256) & 3;

    auto load_chunk = [&](int c) {
        const uint32_t st = sbase + (uint32_t)(c % STAGES) * STAGE_BYTES;
        const int k0 = c << 5;
        {
            long gA = (long)l_row0 * ldA + k0 + l_kc0 * 8;
            long gB = (long)l_row0 * ldB + k0 + l_kc0 * 8;
            uint32_t so = swz(l_row0, l_kc0);
            cp16(st +         so, pAh + gA);
            cp16(st +  8192 + so, pAl + gA);
            cp16(st + 16384 + so, pBh + gB);
            cp16(st + 24576 + so, pBl + gB);
        }
        {
            long gA = (long)l_row1 * ldA + k0 + l_kc1 * 8;
            long gB = (long)l_row1 * ldB + k0 + l_kc1 * 8;
            uint32_t so = swz(l_row1, l_kc1);
            cp16(st +         so, pAh + gA);
            cp16(st +  8192 + so, pAl + gA);
            cp16(st + 16384 + so, pBh + gB);
            cp16(st + 24576 + so, pBl + gB);
        }
        CP_COMMIT();
    };

    float acc[4][4][4];
    #pragma unroll
    for (int i = 0; i < 4; i++)
        #pragma unroll
        for (int j = 0; j < 4; j++)
            #pragma unroll
            for (int p = 0; p < 4; p++) acc[i][j][p] = 0.f;

    // prologue: fill 2 of 3 stages
    load_chunk(0);
    if (nchunks > 1) load_chunk(1);

    const int lrow = lane & 15;
    const int lsel = lane >> 4;

    for (int c = 0; c < nchunks; c++) {
        if (c + 1 < nchunks) asm volatile("cp.async.wait_group 1;" ::: "memory");
        else                 asm volatile("cp.async.wait_group 0;" ::: "memory");
        __syncthreads();   // single barrier per chunk: also retires all reads
                           // of stage (c-1)%3, which load_chunk(c+2) overwrites.

        if (c + 2 < nchunks) load_chunk(c + 2);

        const uint32_t st  = sbase + (uint32_t)(c % STAGES) * STAGE_BYTES;
        const uint32_t sAh = st, sAl = st + 8192, sBh = st + 16384, sBl = st + 24576;

        #pragma unroll
        for (int ks = 0; ks < 2; ks++) {
            const int kc = ks * 2 + lsel;
            uint32_t bh[4][2], bl[4][2];
            #pragma unroll
            for (int np = 0; np < 2; np++) {
                int r = wn * 32 + np * 16 + lrow;
                uint32_t t4[4];
                ldsm_x4(t4, sBh + swz(r, kc));
                bh[np*2][0] = t4[0]; bh[np*2][1] = t4[2];
                bh[np*2+1][0] = t4[1]; bh[np*2+1][1] = t4[3];
                ldsm_x4(t4, sBl + swz(r, kc));
                bl[np*2][0] = t4[0]; bl[np*2][1] = t4[2];
                bl[np*2+1][0] = t4[1]; bl[np*2+1][1] = t4[3];
            }
            // one A fragment pair live at a time (register-lean)
            #pragma unroll
            for (int mt = 0; mt < 4; mt++) {
                int r = wm * 64 + mt * 16 + lrow;
                uint32_t a_hi[4], a_lo[4];
                ldsm_x4(a_hi, sAh + swz(r, kc));
                ldsm_x4(a_lo, sAl + swz(r, kc));
                #pragma unroll
                for (int nt = 0; nt < 4; nt++) {
                    mma16816(acc[mt][nt], a_hi, bh[nt]);
                    mma16816(acc[mt][nt], a_hi, bl[nt]);
                    mma16816(acc[mt][nt], a_lo, bh[nt]);
                }
            }
        }
    }

    // ---- epilogue: stage fp32 tile in smem, then coalesced global writes ----
    __syncthreads();   // protect stage memory before reuse as epilogue buffer
    float* buf = (float*)smem;
    {
        const int rq = lane >> 2;          // 0..7
        const int cq = (lane & 3) * 2;     // 0,2,4,6
        #pragma unroll
        for (int mt = 0; mt < 4; mt++)
            #pragma unroll
            for (int nt = 0; nt < 4; nt++) {
                int r0 = wm * 64 + mt * 16 + rq;
                int c0 = wn * 32 + nt * 8 + cq;
                *(float2*)&buf[r0 * EPI_LD + c0]       = make_float2(acc[mt][nt][0], acc[mt][nt][1]);
                *(float2*)&buf[(r0 + 8) * EPI_LD + c0] = make_float2(acc[mt][nt][2], acc[mt][nt][3]);
            }
    }
    __syncthreads();

    if (mode == 0) {
        int r = tid >> 1, c0 = (tid & 1) * 64;
        long row = (long)by * 128 + r;
        float4* dst = (float4*)(Cf + bz * strideC + row * ldC + (long)bx * 128 + c0);
        #pragma unroll
        for (int i = 0; i < 16; i++)
            dst[i] = *(float4*)&buf[r * EPI_LD + c0 + i * 4];
    } else if (mode == 1) {
        int r = tid >> 1, c0 = (tid & 1) * 64;
        long row = (long)by * 128 + r;
        bf16* dh = Chi + bz * strideC + row * ldC + (long)bx * 128 + c0;
        bf16* dl = Clo + bz * strideC + row * ldC + (long)bx * 128 + c0;
        #pragma unroll
        for (int v = 0; v < 8; v++) {
            uint4 uh, ul;
            uint32_t* ph = (uint32_t*)&uh; uint32_t* pl = (uint32_t*)&ul;
            #pragma unroll
            for (int p = 0; p < 4; p++) {
                float f0 = buf[r * EPI_LD + c0 + v * 8 + p * 2];
                float f1 = buf[r * EPI_LD + c0 + v * 8 + p * 2 + 1];
                bf16 h0 = __float2bfloat16(f0), h1 = __float2bfloat16(f1);
                bf16 l0 = __float2bfloat16(f0 - __bfloat162float(h0));
                bf16 l1 = __float2bfloat16(f1 - __bfloat162float(h1));
                ph[p] = (uint32_t)*(uint16_t*)&h0 | ((uint32_t)*(uint16_t*)&h1 << 16);
                pl[p] = (uint32_t)*(uint16_t*)&l0 | ((uint32_t)*(uint16_t*)&l1 << 16);
            }
            *(uint4*)(dh + v * 8) = uh;
            *(uint4*)(dl + v * 8) = ul;
        }
    } else {
        // transposed hi/lo out: Ct[e][s_local], batch derived from global row
        int cc = tid >> 1, s0 = (tid & 1) * 64;
        int rowbase = by * 128;
        int b = rowbase / SEQ;
        int sloc = (rowbase % SEQ) + s0;
        long e = (long)bx * 128 + cc;
        bf16* dh = Chi + b * strideC + e * ldC + sloc;
        bf16* dl = Clo + b * strideC + e * ldC + sloc;
        #pragma unroll
        for (int v = 0; v < 8; v++) {
            uint4 uh, ul;
            uint32_t* ph = (uint32_t*)&uh; uint32_t* pl = (uint32_t*)&ul;
            #pragma unroll
            for (int p = 0; p < 4; p++) {
                float f0 = buf[(s0 + v * 8 + p * 2)     * EPI_LD + cc];
                float f1 = buf[(s0 + v * 8 + p * 2 + 1) * EPI_LD + cc];
                bf16 h0 = __float2bfloat16(f0), h1 = __float2bfloat16(f1);
                bf16 l0 = __float2bfloat16(f0 - __bfloat162float(h0));
                bf16 l1 = __float2bfloat16(f1 - __bfloat162float(h1));
                ph[p] = (uint32_t)*(uint16_t*)&h0 | ((uint32_t)*(uint16_t*)&h1 << 16);
                pl[p] = (uint32_t)*(uint16_t*)&l0 | ((uint32_t)*(uint16_t*)&l1 << 16);
            }
            *(uint4*)(dh + v * 8) = uh;
            *(uint4*)(dl + v * 8) = ul;
        }
    }
}

// ---------------- fp32 -> bf16 hi/lo split ----------------
__device__ __forceinline__ void split4(const float* __restrict__ src,
                                       bf16* __restrict__ hi, bf16* __restrict__ lo, long i)
{
    float4 v = *(const float4*)(src + i);
    float f[4] = {v.x, v.y, v.z, v.w};
    uint32_t h2[2], l2[2];
    #pragma unroll
    for (int p = 0; p < 2; p++) {
        bf16 h0 = __float2bfloat16(f[p*2]),   h1 = __float2bfloat16(f[p*2+1]);
        bf16 l0 = __float2bfloat16(f[p*2]   - __bfloat162float(h0));
        bf16 l1 = __float2bfloat16(f[p*2+1] - __bfloat162float(h1));
        h2[p] = (uint32_t)*(uint16_t*)&h0 | ((uint32_t)*(uint16_t*)&h1 << 16);
        l2[p] = (uint32_t)*(uint16_t*)&l0 | ((uint32_t)*(uint16_t*)&l1 << 16);
    }
    *(uint2*)(hi + i) = make_uint2(h2[0], h2[1]);
    *(uint2*)(lo + i) = make_uint2(l2[0], l2[1]);
}

__global__ void __launch_bounds__(256) split_f32(
    const float* __restrict__ src, bf16* __restrict__ hi, bf16* __restrict__ lo, long n)
{
    long i = ((long)blockIdx.x * 256 + threadIdx.x) * 4;
    if (i >= n) return;
    split4(src, hi, lo, i);
}

// one launch for all 3 weight matrices (keeps launch count low so ncu -s 5
// lands on the scores GEMM)
__global__ void __launch_bounds__(256) split_w3(
    const float* __restrict__ w0, const float* __restrict__ w1, const float* __restrict__ w2,
    bf16* __restrict__ hi, bf16* __restrict__ lo, long n)
{
    const float* src = (blockIdx.y == 0) ? w0 : (blockIdx.y == 1) ? w1 : w2;
    long off = (long)blockIdx.y * n;
    long i = ((long)blockIdx.x * 256 + threadIdx.x) * 4;
    if (i >= n) return;
    split4(src, hi + off, lo + off, i);
}

// ---------------- causal softmax: fp32 scores -> bf16 hi/lo probs ----------------
__global__ void __launch_bounds__(256) softmax_causal(
    const float* __restrict__ Sc, bf16* __restrict__ Ph, bf16* __restrict__ Pl)
{
    const long r = blockIdx.x;
    const int  q = (int)(r & (SEQ - 1));
    const float* row = Sc + r * SEQ;
    bf16* ph = Ph + r * SEQ;
    bf16* pl = Pl + r * SEQ;

    __shared__ float bufr[SEQ];
    __shared__ float red[256];

    const int tid = threadIdx.x;
    const int len = q + 1;
    const float scale = 0.03125f;  // 1/sqrt(1024)

    float m = -1e30f;
    for (int k = tid; k < len; k += 256) {
        float v = row[k] * scale;
        bufr[k] = v;
        m = fmaxf(m, v);
    }
    red[tid] = m;
    __syncthreads();
    #pragma unroll
    for (int s = 128; s > 0; s >>= 1) {
        if (tid < s) red[tid] = fmaxf(red[tid], red[tid + s]);
        __syncthreads();
    }
    m = red[0];
    __syncthreads();

    float sum = 0.f;
    for (int k = tid; k < len; k += 256) {
        float e = __expf(bufr[k] - m);
        bufr[k] = e;
        sum += e;
    }
    red[tid] = sum;
    __syncthreads();
    #pragma unroll
    for (int s = 128; s > 0; s >>= 1) {
        if (tid < s) red[tid] += red[tid + s];
        __syncthreads();
    }
    const float inv = 1.0f / red[0];
    __syncthreads();

    for (int k = tid; k < len; k += 256) {
        float p = bufr[k] * inv;
        bf16 h = __float2bfloat16(p);
        bf16 l = __float2bfloat16(p - __bfloat162float(h));
        ph[k] = h; pl[k] = l;
    }
    const bf16 z = __float2bfloat16(0.f);
    for (int k = len + tid; k < SEQ; k += 256) { ph[k] = z; pl[k] = z; }
}

// ---------------------------------------------------------------------------
extern "C" void kernel_launch(void* const* d_in, const int* in_sizes, int n_in,
                              void* d_out, int out_size)
{
    const float* X  = (const float*)d_in[0];
    const float* Wq = (const float*)d_in[1];
    const float* Wk = (const float*)d_in[2];
    const float* Wv = (const float*)d_in[3];
    float* out = (float*)d_out;

    bf16 *xh, *xl, *wh, *wl, *qh, *ql, *kh, *kl, *vth, *vtl, *ph, *pl;
    float *sc;
    cudaGetSymbolAddress((void**)&xh,  g_xh);  cudaGetSymbolAddress((void**)&xl,  g_xl);
    cudaGetSymbolAddress((void**)&wh,  g_wh);  cudaGetSymbolAddress((void**)&wl,  g_wl);
    cudaGetSymbolAddress((void**)&qh,  g_qh);  cudaGetSymbolAddress((void**)&ql,  g_ql);
    cudaGetSymbolAddress((void**)&kh,  g_kh);  cudaGetSymbolAddress((void**)&kl,  g_kl);
    cudaGetSymbolAddress((void**)&vth, g_vth); cudaGetSymbolAddress((void**)&vtl, g_vtl);
    cudaGetSymbolAddress((void**)&sc,  g_sc);
    cudaGetSymbolAddress((void**)&ph,  g_ph);  cudaGetSymbolAddress((void**)&pl,  g_pl);

    cudaFuncSetAttribute(gemm_bf16x3, cudaFuncAttributeMaxDynamicSharedMemorySize, SMEM_TOTAL);

    const long nX = (long)BATCH * SEQ * DIM;
    const long nW = (long)DIM * DIM;
    const long WW = nW;

    dim3 thr(256);
    // launch 0
    split_f32<<<(unsigned)(nX / 1024), thr>>>(X, xh, xl, nX);
    // launch 1 (all three weights)
    dim3 gW((unsigned)(nW / 1024), 3, 1);
    split_w3<<<gW, thr>>>(Wq, Wk, Wv, wh, wl, nW);

    const int M = BATCH * SEQ;  // 8192

    // launches 2-4: projections  (Q,K: mode 1; V: mode 2 transposed)
    dim3 gProj(DIM / 128, M / 128, 1);
    gemm_bf16x3<<<gProj, thr, SMEM_TOTAL>>>(xh, xl, wh + 0*WW, wl + 0*WW,
        nullptr, qh, ql, DIM, DIM, DIM, DIM, 0, 0, 0, 0, 0, 1);
    gemm_bf16x3<<<gProj, thr, SMEM_TOTAL>>>(xh, xl, wh + 1*WW, wl + 1*WW,
        nullptr, kh, kl, DIM, DIM, DIM, DIM, 0, 0, 0, 0, 0, 1);
    gemm_bf16x3<<<gProj, thr, SMEM_TOTAL>>>(xh, xl, wh + 2*WW, wl + 2*WW,
        nullptr, vth, vtl, DIM, DIM, DIM, SEQ, 0, 0, (long)DIM * SEQ, 0, 0, 2);

    // launch 5: scores = Q @ K^T per batch (causal tile skip), fp32 out
    dim3 gScore(SEQ / 128, SEQ / 128, BATCH);
    gemm_bf16x3<<<gScore, thr, SMEM_TOTAL>>>(qh, ql, kh, kl,
        sc, nullptr, nullptr, DIM, DIM, DIM, SEQ,
        (long)SEQ * DIM, (long)SEQ * DIM, (long)SEQ * SEQ, 1, 0, 0);

    // launch 6: softmax -> bf16 hi/lo probs
    softmax_causal<<<BATCH * SEQ, thr>>>(sc, ph, pl);

    // launch 7: out = P @ V^T per batch (causal k clamp), fp32 out
    dim3 gAV(DIM / 128, SEQ / 128, BATCH);
    gemm_bf16x3<<<gAV, thr, SMEM_TOTAL>>>(ph, pl, vth, vtl,
        out, nullptr, nullptr, SEQ, SEQ, SEQ, DIM,
        (long)SEQ * SEQ, (long)DIM * SEQ, (long)SEQ * DIM, 0, 1, 0);
}